// round 5
// baseline (speedup 1.0000x reference)
#include <cuda_runtime.h>

#define FULL_MASK 0xffffffffu

// out[j] = x[j - offset] for 0 <= j-offset < n else 0; offset from device scalars.
// Persistent double-buffered warp tiles: each warp strides over 128-vector
// tiles, loading tile t+1 (4 independent LDG.128 + lane0 boundary scalars)
// before realigning+storing tile t, so loads stay continuously in flight.

struct Tile { float4 v[4]; float ey, ez, ew; };

__device__ __forceinline__ void load_tile(const float4* __restrict__ x4,
                                          const float*  __restrict__ xs,
                                          int wbase, int lane, int m, int r,
                                          int nv, int n, Tile& t)
{
    const int g0 = wbase + lane;
#pragma unroll
    for (int k = 0; k < 4; k++) {
        const int sv = g0 + (k << 5) - m;
        float4 x = make_float4(0.f, 0.f, 0.f, 0.f);
        if (sv >= 0 && sv < nv) x = __ldcs(x4 + sv);
        t.v[k] = x;
    }
    t.ey = 0.f; t.ez = 0.f; t.ew = 0.f;
    if (r != 0 && lane == 0) {
        // words (4-r..3) of source vector (wbase - m - 1)
        const int ebase = 4 * (wbase - m) - 4;
        if (r >= 3) { int i = ebase + 1; if (i >= 0 && i < n) t.ey = __ldcs(xs + i); }
        if (r >= 2) { int i = ebase + 2; if (i >= 0 && i < n) t.ez = __ldcs(xs + i); }
        /* r>=1 */ { int i = ebase + 3; if (i >= 0 && i < n) t.ew = __ldcs(xs + i); }
    }
}

__device__ __forceinline__ void store_tile(float4* __restrict__ out4,
                                           int wbase, int lane, int r,
                                           const Tile& t)
{
    const int g0 = wbase + lane;
    if (r == 0) {
#pragma unroll
        for (int k = 0; k < 4; k++) __stcs(out4 + g0 + (k << 5), t.v[k]);
        return;
    }
#pragma unroll
    for (int k = 0; k < 4; k++) {
        float pw;
        {
            float up  = __shfl_up_sync(FULL_MASK, t.v[k].w, 1);
            float b31 = __shfl_sync(FULL_MASK, k > 0 ? t.v[k > 0 ? k - 1 : 0].w : 0.f, 31);
            pw = (lane == 0) ? (k > 0 ? b31 : t.ew) : up;
        }
        float4 o;
        if (r == 1) {
            o = make_float4(pw, t.v[k].x, t.v[k].y, t.v[k].z);
        } else {
            float up  = __shfl_up_sync(FULL_MASK, t.v[k].z, 1);
            float b31 = __shfl_sync(FULL_MASK, k > 0 ? t.v[k > 0 ? k - 1 : 0].z : 0.f, 31);
            float pz = (lane == 0) ? (k > 0 ? b31 : t.ez) : up;
            if (r == 2) {
                o = make_float4(pz, pw, t.v[k].x, t.v[k].y);
            } else {
                float upy  = __shfl_up_sync(FULL_MASK, t.v[k].y, 1);
                float b31y = __shfl_sync(FULL_MASK, k > 0 ? t.v[k > 0 ? k - 1 : 0].y : 0.f, 31);
                float py = (lane == 0) ? (k > 0 ? b31y : t.ey) : upy;
                o = make_float4(py, pz, pw, t.v[k].x);
            }
        }
        __stcs(out4 + g0 + (k << 5), o);
    }
}

__global__ void __launch_bounds__(256, 4)
shift_persist(const float4* __restrict__ x4,
              const float*  __restrict__ xs,
              const float*  __restrict__ w_row,
              const float*  __restrict__ w_col,
              int row_length, int n,
              float4* __restrict__ out4)
{
    const int nv = n >> 2;
    const int niter = nv >> 7;                     // full 128-vector tiles
    const int offset = (int)(w_row[0] + (float)row_length * w_col[0]);
    const int r = offset & 3;
    const int m = (offset - r) >> 2;               // floor(offset/4)

    const int lane    = threadIdx.x & 31;
    const int wstride = (gridDim.x * blockDim.x) >> 5;
    int i = (blockIdx.x * blockDim.x + threadIdx.x) >> 5;
    if (i >= niter) return;

    Tile A, B;
    load_tile(x4, xs, i << 7, lane, m, r, nv, n, A);

    for (;;) {
        int j = i + wstride;
        if (j < niter) load_tile(x4, xs, j << 7, lane, m, r, nv, n, B);
        store_tile(out4, i << 7, lane, r, A);
        i = j;
        if (i >= niter) break;

        j = i + wstride;
        if (j < niter) load_tile(x4, xs, j << 7, lane, m, r, nv, n, A);
        store_tile(out4, i << 7, lane, r, B);
        i = j;
        if (i >= niter) break;
    }
}

// Tail: handles output vectors [vstart, nv) plus any non-multiple-of-4 case
// is excluded on host (n here is 2^26, divisible). Simple guarded per-vector.
__global__ void shift_tail(const float* __restrict__ xs,
                           const float* __restrict__ w_row,
                           const float* __restrict__ w_col,
                           int row_length, int n, int vstart,
                           float4* __restrict__ out4)
{
    const int offset = (int)(w_row[0] + (float)row_length * w_col[0]);
    const int g = vstart + blockIdx.x * blockDim.x + threadIdx.x;
    const int nv = n >> 2;
    if (g >= nv) return;
    const int s = (g << 2) - offset;
    float4 v;
    v.x = (s + 0 >= 0 && s + 0 < n) ? xs[s + 0] : 0.f;
    v.y = (s + 1 >= 0 && s + 1 < n) ? xs[s + 1] : 0.f;
    v.z = (s + 2 >= 0 && s + 2 < n) ? xs[s + 2] : 0.f;
    v.w = (s + 3 >= 0 && s + 3 < n) ? xs[s + 3] : 0.f;
    out4[g] = v;
}

extern "C" void kernel_launch(void* const* d_in, const int* in_sizes, int n_in,
                              void* d_out, int out_size)
{
    const float* x     = (const float*)d_in[0];
    const float* w_row = (const float*)d_in[1];
    const float* w_col = (const float*)d_in[2];

    const int n = in_sizes[0];
    int row_length = 1;
    while ((long long)row_length * row_length < (long long)n) row_length <<= 1;

    const int nv = n >> 2;
    const int niter = nv >> 7;

    // Persistent-resident grid: 4 blocks/SM * 148 SMs (capped by work).
    int blocks = 4 * 148;
    const int warps_per_block = 256 / 32;
    int need_blocks = (niter + warps_per_block - 1) / warps_per_block;
    if (blocks > need_blocks) blocks = need_blocks;
    if (blocks > 0)
        shift_persist<<<blocks, 256>>>((const float4*)x, x, w_row, w_col,
                                       row_length, n, (float4*)d_out);

    const int vstart = niter << 7;
    const int tail = nv - vstart;
    if (tail > 0) {
        int tblocks = (tail + 255) / 256;
        shift_tail<<<tblocks, 256>>>(x, w_row, w_col, row_length, n, vstart,
                                     (float4*)d_out);
    }
}

// round 6
// speedup vs baseline: 1.0105x; 1.0105x over previous
#include <cuda_runtime.h>
#include <cstdint>

// out[j] = x[j - offset] for 0 <= j-offset < n else 0; offset from device scalars.
// TMA-pipelined: per 16KB output tile, one cp.async.bulk loads the source-aligned
// window (TILE_V+1 float4) into SMEM; threads realign by one word-shift r and
// store aligned STG.128. Boundary tiles use a guarded direct path.

#define STAGES     4
#define TILE_V     1024                  // output float4 per tile (16KB)
#define STAGE_VEC  (TILE_V + 1)          // +1 leading source vector
#define TMA_BYTES  (STAGE_VEC * 16)      // 16400 (multiple of 16)
#define STAGE_BYTES 16512                // padded to 128B multiple
#define SMEM_TOTAL (STAGES * STAGE_BYTES + STAGES * 8)
#define NTHREADS   256

__device__ __forceinline__ uint32_t smem_u32(const void* p) {
    return (uint32_t)__cvta_generic_to_shared(p);
}
__device__ __forceinline__ void mbar_init(uint32_t mbar, uint32_t count) {
    asm volatile("mbarrier.init.shared.b64 [%0], %1;" :: "r"(mbar), "r"(count) : "memory");
}
__device__ __forceinline__ void mbar_expect_tx(uint32_t mbar, uint32_t bytes) {
    asm volatile("mbarrier.arrive.expect_tx.shared.b64 _, [%0], %1;"
                 :: "r"(mbar), "r"(bytes) : "memory");
}
__device__ __forceinline__ void mbar_wait(uint32_t mbar, uint32_t parity) {
    asm volatile(
        "{\n\t.reg .pred P;\n"
        "W%=:\n\t"
        "mbarrier.try_wait.parity.acquire.cta.shared::cta.b64 P, [%0], %1, 0x989680;\n\t"
        "@!P bra W%=;\n\t}"
        :: "r"(mbar), "r"(parity) : "memory");
}
__device__ __forceinline__ void tma_bulk_g2s(uint32_t smem_dst, const void* gmem_src,
                                             uint32_t bytes, uint32_t mbar) {
    asm volatile(
        "cp.async.bulk.shared::cta.global.mbarrier::complete_tx::bytes [%0], [%1], %2, [%3];"
        :: "r"(smem_dst), "l"(gmem_src), "r"(bytes), "r"(mbar) : "memory");
}

__device__ __forceinline__ float4 combine(const float4 p, const float4 v, int r) {
    if (r == 0) return v;
    if (r == 1) return make_float4(p.w, v.x, v.y, v.z);
    if (r == 2) return make_float4(p.z, p.w, v.x, v.y);
    return make_float4(p.y, p.z, p.w, v.x);
}

__global__ void __launch_bounds__(NTHREADS)
shift_tma(const float4* __restrict__ x4,
          const float*  __restrict__ xs,
          const float*  __restrict__ w_row,
          const float*  __restrict__ w_col,
          int row_length, int n,
          float4* __restrict__ out4)
{
    extern __shared__ __align__(128) char smem_raw[];
    const int tid = threadIdx.x;

    const int nv = n >> 2;
    const int ntile = nv / TILE_V;
    const int offset = (int)(w_row[0] + (float)row_length * w_col[0]);
    const int r = offset & 3;
    const int m = (offset - r) >> 2;           // floor(offset/4)

    const uint32_t mbar0 = smem_u32(smem_raw + STAGES * STAGE_BYTES);
    if (tid == 0) {
        for (int s = 0; s < STAGES; s++) mbar_init(mbar0 + s * 8, 1);
        // make inits visible to the async proxy before any TMA targets them
        asm volatile("fence.proxy.async.shared::cta;" ::: "memory");
    }
    __syncthreads();

    int head = 0, tail = 0;        // interior tiles issued / consumed
    int jt = blockIdx.x;           // producer tile cursor

    // producer pump: fill free stages with interior-tile bulk loads
    auto interior_of = [&](int t, int& src0) {
        src0 = t * TILE_V - m - 1;
        return (src0 >= 0) && (src0 + STAGE_VEC <= nv);
    };
#define PUMP()                                                                  \
    while (head - tail < STAGES && jt < ntile) {                                \
        int src0;                                                               \
        if (interior_of(jt, src0)) {                                            \
            const int slot = head % STAGES;                                     \
            if (tid == 0) {                                                     \
                mbar_expect_tx(mbar0 + slot * 8, TMA_BYTES);                    \
                tma_bulk_g2s(smem_u32(smem_raw + slot * STAGE_BYTES),           \
                             (const void*)(x4 + src0), TMA_BYTES,               \
                             mbar0 + slot * 8);                                 \
            }                                                                   \
            head++;                                                             \
        }                                                                       \
        jt += gridDim.x;                                                        \
    }

    PUMP();

    for (int t = blockIdx.x; t < ntile; t += gridDim.x) {
        const int tbase = t * TILE_V;
        int src0;
        if (interior_of(t, src0)) {
            const int slot = tail % STAGES;
            mbar_wait(mbar0 + slot * 8, (tail / STAGES) & 1);
            const float4* sp = (const float4*)(smem_raw + slot * STAGE_BYTES);
#pragma unroll
            for (int k = 0; k < 4; k++) {
                const int l = tid + k * NTHREADS;
                const float4 p = sp[l];
                const float4 v = sp[l + 1];
                __stcs(out4 + tbase + l, combine(p, v, r));
            }
            tail++;
            __syncthreads();       // all reads done before slot reuse
            PUMP();
        } else {
            // boundary tile: guarded per-word direct path (rare)
#pragma unroll
            for (int k = 0; k < 4; k++) {
                const int g = tbase + tid + k * NTHREADS;
                const int s = (g << 2) - offset;
                float4 o;
                o.x = (s + 0 >= 0 && s + 0 < n) ? __ldcs(xs + s + 0) : 0.f;
                o.y = (s + 1 >= 0 && s + 1 < n) ? __ldcs(xs + s + 1) : 0.f;
                o.z = (s + 2 >= 0 && s + 2 < n) ? __ldcs(xs + s + 2) : 0.f;
                o.w = (s + 3 >= 0 && s + 3 < n) ? __ldcs(xs + s + 3) : 0.f;
                __stcs(out4 + g, o);
            }
        }
    }
#undef PUMP
}

// Tail for nv % TILE_V (zero for this shape, kept for generality).
__global__ void shift_tail(const float* __restrict__ xs,
                           const float* __restrict__ w_row,
                           const float* __restrict__ w_col,
                           int row_length, int n, int vstart,
                           float4* __restrict__ out4)
{
    const int offset = (int)(w_row[0] + (float)row_length * w_col[0]);
    const int g = vstart + blockIdx.x * blockDim.x + threadIdx.x;
    const int nv = n >> 2;
    if (g >= nv) return;
    const int s = (g << 2) - offset;
    float4 v;
    v.x = (s + 0 >= 0 && s + 0 < n) ? xs[s + 0] : 0.f;
    v.y = (s + 1 >= 0 && s + 1 < n) ? xs[s + 1] : 0.f;
    v.z = (s + 2 >= 0 && s + 2 < n) ? xs[s + 2] : 0.f;
    v.w = (s + 3 >= 0 && s + 3 < n) ? xs[s + 3] : 0.f;
    out4[g] = v;
}

extern "C" void kernel_launch(void* const* d_in, const int* in_sizes, int n_in,
                              void* d_out, int out_size)
{
    const float* x     = (const float*)d_in[0];
    const float* w_row = (const float*)d_in[1];
    const float* w_col = (const float*)d_in[2];

    const int n = in_sizes[0];
    int row_length = 1;
    while ((long long)row_length * row_length < (long long)n) row_length <<= 1;

    const int nv = n >> 2;
    const int ntile = nv / TILE_V;

    static bool attr_set = false;
    if (!attr_set) {
        cudaFuncSetAttribute(shift_tma, cudaFuncAttributeMaxDynamicSharedMemorySize,
                             SMEM_TOTAL);
        attr_set = true;
    }

    int blocks = 3 * 148;                   // 3 blocks/SM @ ~66KB smem each
    if (blocks > ntile) blocks = ntile;
    if (blocks > 0)
        shift_tma<<<blocks, NTHREADS, SMEM_TOTAL>>>((const float4*)x, x, w_row, w_col,
                                                    row_length, n, (float4*)d_out);

    const int vstart = ntile * TILE_V;
    const int tail = nv - vstart;
    if (tail > 0) {
        int tblocks = (tail + 255) / 256;
        shift_tail<<<tblocks, 256>>>(x, w_row, w_col, row_length, n, vstart,
                                     (float4*)d_out);
    }
}

// round 8
// speedup vs baseline: 1.1157x; 1.1041x over previous
#include <cuda_runtime.h>

#define FULL_MASK 0xffffffffu

// out[j] = x[j - offset] for 0 <= j-offset < n else 0; offset from device scalars.
// Warp tile of 128 consecutive output float4s; thread owns k=0..3 vectors at
// lane-contiguous addresses (fully coalesced LDG.128/STG.128, 4 independent
// front-batched loads). Misalignment r = offset & 3 repaired via minimal warp
// shuffles. Interior warps (source window fully in range) run unguarded; the
// ~2 boundary warps take a fully-guarded path. n % 4 == 0.

__global__ void __launch_bounds__(256)
shift_clean(const float4* __restrict__ x4,
            const float*  __restrict__ xs,
            const float*  __restrict__ w_row,
            const float*  __restrict__ w_col,
            int row_length, int n,
            float4* __restrict__ out4)
{
    const int nv = n >> 2;
    const int offset = (int)(w_row[0] + (float)row_length * w_col[0]);
    const int r = offset & 3;
    const int m = (offset - r) >> 2;            // floor(offset/4)

    const int warp_id = (blockIdx.x * blockDim.x + threadIdx.x) >> 5;
    const int lane    = threadIdx.x & 31;
    const int wbase   = warp_id << 7;           // 128 vectors per warp
    const int g0      = wbase + lane;

    // Sources touched by this warp: vectors [wbase-m-1, wbase+128-m).
    const bool interior = (wbase - m - 1 >= 0) && (wbase + 128 - m <= nv) &&
                          (wbase + 128 <= nv);

    if (interior) {
        // ---- hot path: no guards, no selects ----
        float4 v0 = __ldcs(x4 + g0 - m);
        float4 v1 = __ldcs(x4 + g0 - m + 32);
        float4 v2 = __ldcs(x4 + g0 - m + 64);
        float4 v3 = __ldcs(x4 + g0 - m + 96);

        if (r == 0) {
            __stcs(out4 + g0,      v0);
            __stcs(out4 + g0 + 32, v1);
            __stcs(out4 + g0 + 64, v2);
            __stcs(out4 + g0 + 96, v3);
            return;
        }

        // boundary words of vector (wbase-m-1), needed by lane 0 of k=0
        float e_y = 0.f, e_z = 0.f, e_w = 0.f;
        if (lane == 0) {
            const float* eb = xs + 4 * (wbase - m) - 4;
            e_w = __ldcs(eb + 3);
            if (r >= 2) e_z = __ldcs(eb + 2);
            if (r >= 3) e_y = __ldcs(eb + 1);
        }

        float4 v[4] = {v0, v1, v2, v3};
#define PREVW(comp, k, evar, dst)                                             \
        do {                                                                  \
            float _up  = __shfl_up_sync(FULL_MASK, v[k].comp, 1);             \
            float _b31 = __shfl_sync(FULL_MASK,                               \
                                     (k) > 0 ? v[(k)>0?(k)-1:0].comp : 0.f,   \
                                     31);                                     \
            dst = (lane == 0) ? ((k) > 0 ? _b31 : (evar)) : _up;              \
        } while (0)

#pragma unroll
        for (int k = 0; k < 4; k++) {
            float pw, pz, py;
            PREVW(w, k, e_w, pw);
            float4 o;
            if (r == 1) {
                o = make_float4(pw, v[k].x, v[k].y, v[k].z);
            } else if (r == 2) {
                PREVW(z, k, e_z, pz);
                o = make_float4(pz, pw, v[k].x, v[k].y);
            } else {
                PREVW(z, k, e_z, pz);
                PREVW(y, k, e_y, py);
                o = make_float4(py, pz, pw, v[k].x);
            }
            __stcs(out4 + g0 + (k << 5), o);
        }
#undef PREVW
        return;
    }

    // ---- boundary path: fully guarded per-word (rare: ~2 warps) ----
#pragma unroll
    for (int k = 0; k < 4; k++) {
        const int g = g0 + (k << 5);
        if (g >= nv) continue;
        const int s = (g << 2) - offset;
        float4 o;
        o.x = (s + 0 >= 0 && s + 0 < n) ? __ldcs(xs + s + 0) : 0.f;
        o.y = (s + 1 >= 0 && s + 1 < n) ? __ldcs(xs + s + 1) : 0.f;
        o.z = (s + 2 >= 0 && s + 2 < n) ? __ldcs(xs + s + 2) : 0.f;
        o.w = (s + 3 >= 0 && s + 3 < n) ? __ldcs(xs + s + 3) : 0.f;
        __stcs(out4 + g, o);
    }
}

extern "C" void kernel_launch(void* const* d_in, const int* in_sizes, int n_in,
                              void* d_out, int out_size)
{
    const float* x     = (const float*)d_in[0];
    const float* w_row = (const float*)d_in[1];
    const float* w_col = (const float*)d_in[2];

    const int n = in_sizes[0];
    int row_length = 1;
    while ((long long)row_length * row_length < (long long)n) row_length <<= 1;

    const int nv = n >> 2;
    const int warps = (nv + 127) >> 7;          // 128 vectors per warp
    const int threads = 256;
    const int blocks = (warps * 32 + threads - 1) / threads;

    shift_clean<<<blocks, threads>>>((const float4*)x, x, w_row, w_col,
                                     row_length, n, (float4*)d_out);
}

// round 9
// speedup vs baseline: 1.1161x; 1.0004x over previous
#include <cuda_runtime.h>

#define FULL_MASK 0xffffffffu

// out[j] = x[j - offset] for 0 <= j-offset < n else 0; offset from device scalars.
// Warp tile: 128 consecutive output float4s; thread owns k=0..3 vectors at
// lane-contiguous addresses (fully coalesced LDG.128/STG.128, 4 independent
// front-batched loads). Loads issue unconditionally on clamped addresses;
// the zero-fill correction is applied only by edge warps (warp-uniform test
// evaluated after the loads are in flight). r = offset & 3 repaired with
// minimal warp shuffles. Grid is exact (nv % 128 == 0 for this shape).

__global__ void __launch_bounds__(256)
shift_v3(const float4* __restrict__ x4,
         const float*  __restrict__ xs,
         const float*  __restrict__ w_row,
         const float*  __restrict__ w_col,
         int row_length, int n,
         float4* __restrict__ out4)
{
    const int nv = n >> 2;
    const int offset = (int)(w_row[0] + (float)row_length * w_col[0]);
    const int r = offset & 3;
    const int m = (offset - r) >> 2;               // floor(offset/4)

    const int warp_id = (blockIdx.x * blockDim.x + threadIdx.x) >> 5;
    const int lane    = threadIdx.x & 31;
    const int wbase   = warp_id << 7;
    const int g0      = wbase + lane;

    // Issue all 4 loads immediately on range-clamped addresses (no dependent
    // predicate chain ahead of the LDGs).
    int sv[4];
    float4 v[4];
#pragma unroll
    for (int k = 0; k < 4; k++) {
        sv[k] = g0 + (k << 5) - m;
        int c = sv[k] < 0 ? 0 : (sv[k] >= nv ? nv - 1 : sv[k]);
        v[k] = __ldcg(x4 + c);
    }

    // Edge correction: warp-uniform test; only ~2 warps per launch enter.
    const bool edge = (wbase - m - 1 < 0) || (wbase + 128 - m > nv);
    if (edge) {
#pragma unroll
        for (int k = 0; k < 4; k++)
            if (sv[k] < 0 || sv[k] >= nv)
                v[k] = make_float4(0.f, 0.f, 0.f, 0.f);
    }

    if (r == 0) {
#pragma unroll
        for (int k = 0; k < 4; k++)
            __stcs(out4 + g0 + (k << 5), v[k]);
        return;
    }

    // Boundary words of vector (wbase - m - 1) for lane 0, k = 0.
    float e_y = 0.f, e_z = 0.f, e_w = 0.f;
    if (lane == 0) {
        const int ebase = 4 * (wbase - m) - 4;
        { int i = ebase + 3; if (i >= 0 && i < n) e_w = __ldcg(xs + i); }
        if (r >= 2) { int i = ebase + 2; if (i >= 0 && i < n) e_z = __ldcg(xs + i); }
        if (r >= 3) { int i = ebase + 1; if (i >= 0 && i < n) e_y = __ldcg(xs + i); }
    }

#define PREVW(comp, k, evar, dst)                                             \
    do {                                                                      \
        float _up  = __shfl_up_sync(FULL_MASK, v[k].comp, 1);                 \
        float _b31 = __shfl_sync(FULL_MASK,                                   \
                                 (k) > 0 ? v[(k)>0?(k)-1:0].comp : 0.f, 31);  \
        dst = (lane == 0) ? ((k) > 0 ? _b31 : (evar)) : _up;                  \
    } while (0)

#pragma unroll
    for (int k = 0; k < 4; k++) {
        float pw, pz, py;
        PREVW(w, k, e_w, pw);
        float4 o;
        if (r == 1) {
            o = make_float4(pw, v[k].x, v[k].y, v[k].z);
        } else if (r == 2) {
            PREVW(z, k, e_z, pz);
            o = make_float4(pz, pw, v[k].x, v[k].y);
        } else {
            PREVW(z, k, e_z, pz);
            PREVW(y, k, e_y, py);
            o = make_float4(py, pz, pw, v[k].x);
        }
        __stcs(out4 + g0 + (k << 5), o);
    }
#undef PREVW
}

// Generic guarded fallback for shapes where nv % 128 != 0 (not hit here).
__global__ void shift_fallback(const float* __restrict__ xs,
                               const float* __restrict__ w_row,
                               const float* __restrict__ w_col,
                               int row_length, int n, int vstart,
                               float4* __restrict__ out4)
{
    const int offset = (int)(w_row[0] + (float)row_length * w_col[0]);
    const int g = vstart + blockIdx.x * blockDim.x + threadIdx.x;
    const int nv = n >> 2;
    if (g >= nv) return;
    const int s = (g << 2) - offset;
    float4 v;
    v.x = (s + 0 >= 0 && s + 0 < n) ? xs[s + 0] : 0.f;
    v.y = (s + 1 >= 0 && s + 1 < n) ? xs[s + 1] : 0.f;
    v.z = (s + 2 >= 0 && s + 2 < n) ? xs[s + 2] : 0.f;
    v.w = (s + 3 >= 0 && s + 3 < n) ? xs[s + 3] : 0.f;
    out4[g] = v;
}

extern "C" void kernel_launch(void* const* d_in, const int* in_sizes, int n_in,
                              void* d_out, int out_size)
{
    const float* x     = (const float*)d_in[0];
    const float* w_row = (const float*)d_in[1];
    const float* w_col = (const float*)d_in[2];

    const int n = in_sizes[0];
    int row_length = 1;
    while ((long long)row_length * row_length < (long long)n) row_length <<= 1;

    const int nv = n >> 2;
    const int full_warps = nv >> 7;                // whole 128-vector tiles
    const int threads = 256;

    if (full_warps > 0) {
        const int blocks = (full_warps * 32 + threads - 1) / threads;
        shift_v3<<<blocks, threads>>>((const float4*)x, x, w_row, w_col,
                                      row_length, n, (float4*)d_out);
    }
    const int vstart = full_warps << 7;
    const int tail = nv - vstart;
    if (tail > 0) {
        int tblocks = (tail + 255) / 256;
        shift_fallback<<<tblocks, 256>>>(x, w_row, w_col, row_length, n,
                                         vstart, (float4*)d_out);
    }
}